// round 16
// baseline (speedup 1.0000x reference)
#include <cuda_runtime.h>
#include <cstdint>

#define BB   32
#define HW_  1600
#define A_   5
#define NGT  128
#define CC   80
#define TPB  160   // preds per block; 50 blocks per batch

constexpr int NPRED       = BB * HW_ * A_;            // 256000
constexpr int IOUS_OFF    = NPRED * 4;
constexpr int CLASSES_OFF = IOUS_OFF + NPRED;
constexpr int BOXM_OFF    = CLASSES_OFF + NPRED * CC;
constexpr int IOUM_OFF    = BOXM_OFF + NPRED;
constexpr int CLSM_OFF    = IOUM_OFF + NPRED;

constexpr int CLS_SLICE_BYTES = TPB * CC * 4;   // 51200 per block
constexpr int STAGE_FLOATS    = 3200;           // 12800 B zero staging
constexpr int STAGE_BYTES     = STAGE_FLOATS * 4;
constexpr int NBULK           = CLS_SLICE_BYTES / STAGE_BYTES;  // 4

// ---------------------------------------------------------------------------
// FILL kernel (stream 2): classes region ONLY. R13's proven TMA-bulk zero
// path + in-kernel 1.0-set. Pure memory streamer — overlaps the compute
// kernel on the main stream (disjoint output regions, no race).
// ---------------------------------------------------------------------------
__global__ void __launch_bounds__(TPB) yolo_fill_kernel(
    const float* __restrict__ gt,        // BB * NGT * 5
    const float* __restrict__ anchors,   // 5*2
    const int*   __restrict__ num_boxes, // BB
    float*       __restrict__ out)
{
    __shared__ __align__(16) float stage[STAGE_FLOATS];  // stays all-zero

    const int tid = threadIdx.x;
    const int t0  = blockIdx.x * TPB;
    const int b   = blockIdx.x / 50;

    // zero the reusable staging buffer
    {
        float4* s4 = (float4*)stage;
        const float4 z = make_float4(0.f, 0.f, 0.f, 0.f);
        #pragma unroll
        for (int i = 0; i < 5; i++)
            s4[i * TPB + tid] = z;
    }
    __syncthreads();

    // issue 4 bulk zero-stores covering this block's 51.2KB classes slice
    if (tid == 0) {
        asm volatile("fence.proxy.async.shared::cta;" ::: "memory");
        uint32_t saddr;
        asm("{ .reg .u64 _t; cvta.to.shared.u64 _t, %1; cvt.u32.u64 %0, _t; }"
            : "=r"(saddr) : "l"(stage));
        const char* dst = (const char*)(out + CLASSES_OFF)
                        + (long)blockIdx.x * CLS_SLICE_BYTES;
        #pragma unroll
        for (int i = 0; i < NBULK; i++)
            asm volatile("cp.async.bulk.global.shared::cta.bulk_group [%0], [%1], %2;"
                         :: "l"(dst + (long)i * STAGE_BYTES), "r"(saddr),
                            "r"((unsigned)STAGE_BYTES) : "memory");
        asm volatile("cp.async.bulk.commit_group;" ::: "memory");
    }

    // gt metadata (lite): flat index + class for the 1.0-set
    int  my_flat = 0, my_local = -1, my_cls = 0;
    bool my_valid = false;
    if (tid < NGT) {
        const float* p = gt + ((long)b * NGT + tid) * 5;
        const float gx1 = p[0], gy1 = p[1], gx2 = p[2], gy2 = p[3];
        my_cls = (int)p[4];

        const float cx = (gx1 + gx2) * 0.5f / 32.0f;
        const float cy = (gy1 + gy2) * 0.5f / 32.0f;
        const float fcx = floorf(cx), fcy = floorf(cy);
        const int cell = (int)(fcy * 40.0f + fcx);
        const int nb = num_boxes[b];
        my_valid = (tid < nb) && (cell >= 0) && (cell < HW_);

        // anchor argmax (first max wins; IEEE division matches reference)
        const float gw = (gx2 / 32.0f - gx1 / 32.0f) + 1.0f;
        const float gh = (gy2 / 32.0f - gy1 / 32.0f) + 1.0f;
        const float gwh = gw * gh;
        int a_ind = 0;
        float bestA = -1.0f;
        #pragma unroll
        for (int a = 0; a < A_; a++) {
            const float aw = anchors[2 * a], ah = anchors[2 * a + 1];
            const float inta = fminf(aw, gw) * fminf(ah, gh);
            const float aiou = inta / (aw * ah + gwh - inta);
            if (aiou > bestA) { bestA = aiou; a_ind = a; }
        }
        my_flat  = (b * HW_ + cell) * A_ + a_ind;
        my_local = my_flat - t0;
    }

    // 1.0-set after this block's bulk zeros complete
    if (tid == 0)
        asm volatile("cp.async.bulk.wait_group 0;" ::: "memory");
    __syncthreads();
    if (tid < NGT && my_valid && my_local >= 0 && my_local < TPB)
        out[CLASSES_OFF + (long)my_flat * CC + my_cls] = 1.0f;
}

// ---------------------------------------------------------------------------
// COMPUTE kernel (main stream): everything except classes. R13 structure
// minus TMA (no staging, no wait tail). Early streaming defaults, warp-hull
// prefilter, last-wins scatter, same-thread fixups.
// ---------------------------------------------------------------------------
__global__ void __launch_bounds__(TPB) yolo_compute_kernel(
    const float4* __restrict__ bbox_pred,
    const float*  __restrict__ iou_pred,
    const float*  __restrict__ gt,        // BB * NGT * 5
    const float*  __restrict__ anchors,   // 5*2
    const int*    __restrict__ num_boxes, // BB
    float*        __restrict__ out)
{
    __shared__ float4 g4[NGT];     // x1, y1, x2+1, y2+1
    __shared__ float  sg[NGT];     // 0.375 * garea
    __shared__ float  sga[NGT];    // garea
    __shared__ float4 stbox[NGT];  // target tbox per gt
    __shared__ int    swin[TPB];   // winning gt index per local pred slot

    const int tid = threadIdx.x;
    const int t0  = blockIdx.x * TPB;
    const int t   = t0 + tid;
    const int b   = blockIdx.x / 50;
    const int lane = tid & 31;

    // ---- early loads ----
    const float4 bp = bbox_pred[t];
    const float  ip = iou_pred[t];

    // ---- default-store burst (streaming) ----
    float4* out4 = (float4*)out;
    __stcs(&out4[t], make_float4(0.5f, 0.5f, 1.0f, 1.0f));   // boxes_t default
    __stcs(&out[IOUS_OFF + t], 0.0f);                        // ious_t
    __stcs(&out[BOXM_OFF + t], 0.01f);                       // box_mask
    __stcs(&out[CLSM_OFF + t], 0.0f);                        // class_mask
    __stcs(&out[IOUM_OFF + t], -ip);                         // iou_mask default

    swin[tid] = -1;

    // ---- phase A: gt metadata (tid < 128) ----
    bool my_valid = false;
    int  my_local = -1;
    if (tid < NGT) {
        const float* p = gt + ((long)b * NGT + tid) * 5;
        const float gx1 = p[0], gy1 = p[1], gx2 = p[2], gy2 = p[3];
        g4[tid] = make_float4(gx1, gy1, gx2 + 1.0f, gy2 + 1.0f);
        const float ga = (gx2 - gx1 + 1.0f) * (gy2 - gy1 + 1.0f);
        sga[tid] = ga;
        sg[tid]  = 0.375f * ga;

        const float cx = (gx1 + gx2) * 0.5f / 32.0f;
        const float cy = (gy1 + gy2) * 0.5f / 32.0f;
        const float fcx = floorf(cx), fcy = floorf(cy);
        const int cell = (int)(fcy * 40.0f + fcx);
        const int nb = num_boxes[b];
        my_valid = (tid < nb) && (cell >= 0) && (cell < HW_);

        // anchor argmax (first max wins; IEEE division matches reference)
        const float gw = (gx2 / 32.0f - gx1 / 32.0f) + 1.0f;
        const float gh = (gy2 / 32.0f - gy1 / 32.0f) + 1.0f;
        const float gwh = gw * gh;
        int a_ind = 0;
        float bestA = -1.0f;
        #pragma unroll
        for (int a = 0; a < A_; a++) {
            const float aw = anchors[2 * a], ah = anchors[2 * a + 1];
            const float inta = fminf(aw, gw) * fminf(ah, gh);
            const float aiou = inta / (aw * ah + gwh - inta);
            if (aiou > bestA) { bestA = aiou; a_ind = a; }
        }

        const int my_flat = (b * HW_ + cell) * A_ + a_ind;
        my_local = my_flat - t0;
        const float tw = (gx2 - gx1 + 1.0f) / 32.0f;
        const float th = (gy2 - gy1 + 1.0f) / 32.0f;
        stbox[tid] = make_float4(cx - fcx, cy - fcy,
                                 tw / anchors[2 * a_ind],
                                 th / anchors[2 * a_ind + 1]);
    }
    __syncthreads();

    // ---- phase B: scatter ownership (last index wins -> max n) ----
    if (tid < NGT && my_valid && my_local >= 0 && my_local < TPB)
        atomicMax(&swin[my_local], tid);
    __syncthreads();

    // ---- phase C: pred geometry ----
    const int hw = (t / A_) % HW_;
    const int a  = t % A_;
    const float col = (float)(hw % 40);
    const float row = (float)(hw / 40);
    const float cxp = (bp.x + col) * (1.0f / 40.0f);
    const float cyp = (bp.y + row) * (1.0f / 40.0f);
    const float bw  = bp.z * anchors[2 * a]     * (1.0f / 40.0f) * 0.5f;
    const float bh  = bp.w * anchors[2 * a + 1] * (1.0f / 40.0f) * 0.5f;
    const float x1  = (cxp - bw) * 1280.0f;
    const float y1  = (cyp - bh) * 1280.0f;
    const float x2p = (cxp + bw) * 1280.0f + 1.0f;
    const float y2p = (cyp + bh) * 1280.0f + 1.0f;
    const float sb  = 0.375f * (x2p - x1) * (y2p - y1);

    // ---- warp hull of the 32 pred boxes ----
    float hx1 = x1, hy1 = y1, hx2 = x2p, hy2 = y2p;
    #pragma unroll
    for (int s = 16; s; s >>= 1) {
        hx1 = fminf(hx1, __shfl_xor_sync(0xffffffffu, hx1, s));
        hy1 = fminf(hy1, __shfl_xor_sync(0xffffffffu, hy1, s));
        hx2 = fmaxf(hx2, __shfl_xor_sync(0xffffffffu, hx2, s));
        hy2 = fmaxf(hy2, __shfl_xor_sync(0xffffffffu, hy2, s));
    }

    // ---- candidate masks via ballot ----
    unsigned masks[4];
    #pragma unroll
    for (int j = 0; j < 4; j++) {
        const float4 g = g4[j * 32 + lane];
        const bool cand = (fminf(hx2, g.z) > fmaxf(hx1, g.x)) &&
                          (fminf(hy2, g.w) > fmaxf(hy1, g.y));
        masks[j] = __ballot_sync(0xffffffffu, cand);
    }

    // ---- hit loop over candidates only ----
    float acc = -1e30f;
    #pragma unroll
    for (int j = 0; j < 4; j++) {
        unsigned m = masks[j];
        while (m) {
            const int n = j * 32 + (__ffs(m) - 1);
            m &= m - 1;
            const float4 g = g4[n];
            const float iw = fmaxf(fminf(x2p, g.z) - fmaxf(x1, g.x), 0.0f);
            const float ih = fminf(y2p, g.w) - fmaxf(y1, g.y);
            acc = fmaxf(acc, fmaf(iw, ih, -sg[n]));
        }
    }
    const bool hit = (acc >= sb);

    // ---- fix-ups (same thread as the default writes -> ordered) ----
    const int win = swin[tid];
    if (win >= 0) {
        const float4 g = g4[win];
        const float iw = fmaxf(fminf(x2p, g.z) - fmaxf(x1, g.x), 0.0f);
        const float ih = fmaxf(fminf(y2p, g.w) - fmaxf(y1, g.y), 0.0f);
        const float inter = iw * ih;
        const float ba = (x2p - x1) * (y2p - y1);
        const float iou = inter / (ba + sga[win] - inter);
        out4[t] = stbox[win];
        out[IOUS_OFF + t] = iou;
        out[BOXM_OFF + t] = 1.0f;
        out[IOUM_OFF + t] = 5.0f * (1.0f - ip);
        out[CLSM_OFF + t] = 1.0f;
    } else if (hit) {
        out[IOUM_OFF + t] = 0.0f;
    }
}

extern "C" void kernel_launch(void* const* d_in, const int* in_sizes, int n_in,
                              void* d_out, int out_size)
{
    const float4* bbox4   = (const float4*)d_in[0];
    const float*  ioup    = (const float*)d_in[1];
    const float*  gtb     = (const float*)d_in[2];
    const float*  anchors = (const float*)d_in[3];
    const int*    nboxes  = (const int*)d_in[4];
    float* out = (float*)d_out;

    // Created on the FIRST call (the uncaptured correctness run); reused in
    // the captured graph as fork/join nodes. No device memory involved.
    static cudaStream_t s2 = [] {
        cudaStream_t s; cudaStreamCreateWithFlags(&s, cudaStreamNonBlocking);
        return s;
    }();
    static cudaEvent_t ev_fork = [] {
        cudaEvent_t e; cudaEventCreateWithFlags(&e, cudaEventDisableTiming);
        return e;
    }();
    static cudaEvent_t ev_join = [] {
        cudaEvent_t e; cudaEventCreateWithFlags(&e, cudaEventDisableTiming);
        return e;
    }();

    // fork: fill (classes, 70MB) runs on s2 concurrently with compute (rest)
    cudaEventRecord(ev_fork, 0);
    cudaStreamWaitEvent(s2, ev_fork, 0);
    yolo_fill_kernel<<<NPRED / TPB, TPB, 0, s2>>>(gtb, anchors, nboxes, out);
    yolo_compute_kernel<<<NPRED / TPB, TPB>>>(bbox4, ioup, gtb, anchors, nboxes, out);
    cudaEventRecord(ev_join, s2);
    cudaStreamWaitEvent(0, ev_join, 0);
}

// round 17
// speedup vs baseline: 1.0552x; 1.0552x over previous
#include <cuda_runtime.h>
#include <cstdint>

#define BB   32
#define HW_  1600
#define A_   5
#define NGT  128
#define CC   80
#define TPB  160   // preds per block/slice; 50 slices per batch
#define FB   400   // fill-kernel blocks; 4 slices per fill block

constexpr int NPRED       = BB * HW_ * A_;            // 256000
constexpr int IOUS_OFF    = NPRED * 4;
constexpr int CLASSES_OFF = IOUS_OFF + NPRED;
constexpr int BOXM_OFF    = CLASSES_OFF + NPRED * CC;
constexpr int IOUM_OFF    = BOXM_OFF + NPRED;
constexpr int CLSM_OFF    = IOUM_OFF + NPRED;

constexpr int NSLICE          = NPRED / TPB;          // 1600
constexpr int CLS_SLICE_BYTES = TPB * CC * 4;         // 51200 per slice
constexpr int STAGE_FLOATS    = 3200;                 // 12800 B zero staging
constexpr int STAGE_BYTES     = STAGE_FLOATS * 4;
constexpr int NBULK           = CLS_SLICE_BYTES / STAGE_BYTES;  // 4

// ---------------------------------------------------------------------------
// FILL kernel (small grid, co-resident with compute): classes region only.
// 400 blocks x 4 slices each; 16 TMA bulk zero-stores per block from one
// reusable 12.8KB zero staging buffer, then the per-gt 1.0-set for its own
// slices (same-block ordering after wait_group 0).
// ---------------------------------------------------------------------------
__global__ void __launch_bounds__(TPB) yolo_fill_kernel(
    const float* __restrict__ gt,        // BB * NGT * 5
    const float* __restrict__ anchors,   // 5*2
    const int*   __restrict__ num_boxes, // BB
    float*       __restrict__ out)
{
    __shared__ __align__(16) float stage[STAGE_FLOATS];  // stays all-zero

    const int tid = threadIdx.x;

    // zero the reusable staging buffer
    {
        float4* s4 = (float4*)stage;
        const float4 z = make_float4(0.f, 0.f, 0.f, 0.f);
        #pragma unroll
        for (int i = 0; i < 5; i++)
            s4[i * TPB + tid] = z;
    }
    __syncthreads();

    // issue bulk zero-stores for all 4 owned slices (one commit)
    if (tid == 0) {
        asm volatile("fence.proxy.async.shared::cta;" ::: "memory");
        uint32_t saddr;
        asm("{ .reg .u64 _t; cvta.to.shared.u64 _t, %1; cvt.u32.u64 %0, _t; }"
            : "=r"(saddr) : "l"(stage));
        for (int s = blockIdx.x; s < NSLICE; s += FB) {
            const char* dst = (const char*)(out + CLASSES_OFF)
                            + (long)s * CLS_SLICE_BYTES;
            #pragma unroll
            for (int i = 0; i < NBULK; i++)
                asm volatile("cp.async.bulk.global.shared::cta.bulk_group [%0], [%1], %2;"
                             :: "l"(dst + (long)i * STAGE_BYTES), "r"(saddr),
                                "r"((unsigned)STAGE_BYTES) : "memory");
        }
        asm volatile("cp.async.bulk.commit_group;" ::: "memory");
        asm volatile("cp.async.bulk.wait_group 0;" ::: "memory");
    }
    __syncthreads();   // all zeros for owned slices are in memory

    // 1.0-set for owned slices (gt rows are tiny; L1/L2 cached across slices)
    for (int s = blockIdx.x; s < NSLICE; s += FB) {
        const int b  = s / 50;
        const int t0 = s * TPB;
        if (tid < NGT) {
            const float* p = gt + ((long)b * NGT + tid) * 5;
            const float gx1 = p[0], gy1 = p[1], gx2 = p[2], gy2 = p[3];
            const int cls = (int)p[4];

            const float cx = (gx1 + gx2) * 0.5f / 32.0f;
            const float cy = (gy1 + gy2) * 0.5f / 32.0f;
            const float fcx = floorf(cx), fcy = floorf(cy);
            const int cell = (int)(fcy * 40.0f + fcx);
            const int nb = num_boxes[b];
            const bool valid = (tid < nb) && (cell >= 0) && (cell < HW_);

            // anchor argmax (first max wins; IEEE division matches reference)
            const float gw = (gx2 / 32.0f - gx1 / 32.0f) + 1.0f;
            const float gh = (gy2 / 32.0f - gy1 / 32.0f) + 1.0f;
            const float gwh = gw * gh;
            int a_ind = 0;
            float bestA = -1.0f;
            #pragma unroll
            for (int a = 0; a < A_; a++) {
                const float aw = anchors[2 * a], ah = anchors[2 * a + 1];
                const float inta = fminf(aw, gw) * fminf(ah, gh);
                const float aiou = inta / (aw * ah + gwh - inta);
                if (aiou > bestA) { bestA = aiou; a_ind = a; }
            }
            const int flat = (b * HW_ + cell) * A_ + a_ind;
            const int loc  = flat - t0;
            if (valid && loc >= 0 && loc < TPB)
                out[CLASSES_OFF + (long)flat * CC + cls] = 1.0f;
        }
    }
}

// ---------------------------------------------------------------------------
// COMPUTE kernel: everything except classes (12.6us standalone, R16-proven).
// ---------------------------------------------------------------------------
__global__ void __launch_bounds__(TPB) yolo_compute_kernel(
    const float4* __restrict__ bbox_pred,
    const float*  __restrict__ iou_pred,
    const float*  __restrict__ gt,        // BB * NGT * 5
    const float*  __restrict__ anchors,   // 5*2
    const int*    __restrict__ num_boxes, // BB
    float*        __restrict__ out)
{
    __shared__ float4 g4[NGT];     // x1, y1, x2+1, y2+1
    __shared__ float  sg[NGT];     // 0.375 * garea
    __shared__ float  sga[NGT];    // garea
    __shared__ float4 stbox[NGT];  // target tbox per gt
    __shared__ int    swin[TPB];   // winning gt index per local pred slot

    const int tid = threadIdx.x;
    const int t0  = blockIdx.x * TPB;
    const int t   = t0 + tid;
    const int b   = blockIdx.x / 50;
    const int lane = tid & 31;

    // ---- early loads ----
    const float4 bp = bbox_pred[t];
    const float  ip = iou_pred[t];

    // ---- default-store burst (streaming) ----
    float4* out4 = (float4*)out;
    __stcs(&out4[t], make_float4(0.5f, 0.5f, 1.0f, 1.0f));   // boxes_t default
    __stcs(&out[IOUS_OFF + t], 0.0f);                        // ious_t
    __stcs(&out[BOXM_OFF + t], 0.01f);                       // box_mask
    __stcs(&out[CLSM_OFF + t], 0.0f);                        // class_mask
    __stcs(&out[IOUM_OFF + t], -ip);                         // iou_mask default

    swin[tid] = -1;

    // ---- phase A: gt metadata (tid < 128) ----
    bool my_valid = false;
    int  my_local = -1;
    if (tid < NGT) {
        const float* p = gt + ((long)b * NGT + tid) * 5;
        const float gx1 = p[0], gy1 = p[1], gx2 = p[2], gy2 = p[3];
        g4[tid] = make_float4(gx1, gy1, gx2 + 1.0f, gy2 + 1.0f);
        const float ga = (gx2 - gx1 + 1.0f) * (gy2 - gy1 + 1.0f);
        sga[tid] = ga;
        sg[tid]  = 0.375f * ga;

        const float cx = (gx1 + gx2) * 0.5f / 32.0f;
        const float cy = (gy1 + gy2) * 0.5f / 32.0f;
        const float fcx = floorf(cx), fcy = floorf(cy);
        const int cell = (int)(fcy * 40.0f + fcx);
        const int nb = num_boxes[b];
        my_valid = (tid < nb) && (cell >= 0) && (cell < HW_);

        // anchor argmax (first max wins; IEEE division matches reference)
        const float gw = (gx2 / 32.0f - gx1 / 32.0f) + 1.0f;
        const float gh = (gy2 / 32.0f - gy1 / 32.0f) + 1.0f;
        const float gwh = gw * gh;
        int a_ind = 0;
        float bestA = -1.0f;
        #pragma unroll
        for (int a = 0; a < A_; a++) {
            const float aw = anchors[2 * a], ah = anchors[2 * a + 1];
            const float inta = fminf(aw, gw) * fminf(ah, gh);
            const float aiou = inta / (aw * ah + gwh - inta);
            if (aiou > bestA) { bestA = aiou; a_ind = a; }
        }

        const int my_flat = (b * HW_ + cell) * A_ + a_ind;
        my_local = my_flat - t0;
        const float tw = (gx2 - gx1 + 1.0f) / 32.0f;
        const float th = (gy2 - gy1 + 1.0f) / 32.0f;
        stbox[tid] = make_float4(cx - fcx, cy - fcy,
                                 tw / anchors[2 * a_ind],
                                 th / anchors[2 * a_ind + 1]);
    }
    __syncthreads();

    // ---- phase B: scatter ownership (last index wins -> max n) ----
    if (tid < NGT && my_valid && my_local >= 0 && my_local < TPB)
        atomicMax(&swin[my_local], tid);
    __syncthreads();

    // ---- phase C: pred geometry ----
    const int hw = (t / A_) % HW_;
    const int a  = t % A_;
    const float col = (float)(hw % 40);
    const float row = (float)(hw / 40);
    const float cxp = (bp.x + col) * (1.0f / 40.0f);
    const float cyp = (bp.y + row) * (1.0f / 40.0f);
    const float bw  = bp.z * anchors[2 * a]     * (1.0f / 40.0f) * 0.5f;
    const float bh  = bp.w * anchors[2 * a + 1] * (1.0f / 40.0f) * 0.5f;
    const float x1  = (cxp - bw) * 1280.0f;
    const float y1  = (cyp - bh) * 1280.0f;
    const float x2p = (cxp + bw) * 1280.0f + 1.0f;
    const float y2p = (cyp + bh) * 1280.0f + 1.0f;
    const float sb  = 0.375f * (x2p - x1) * (y2p - y1);

    // ---- warp hull of the 32 pred boxes ----
    float hx1 = x1, hy1 = y1, hx2 = x2p, hy2 = y2p;
    #pragma unroll
    for (int s = 16; s; s >>= 1) {
        hx1 = fminf(hx1, __shfl_xor_sync(0xffffffffu, hx1, s));
        hy1 = fminf(hy1, __shfl_xor_sync(0xffffffffu, hy1, s));
        hx2 = fmaxf(hx2, __shfl_xor_sync(0xffffffffu, hx2, s));
        hy2 = fmaxf(hy2, __shfl_xor_sync(0xffffffffu, hy2, s));
    }

    // ---- candidate masks via ballot ----
    unsigned masks[4];
    #pragma unroll
    for (int j = 0; j < 4; j++) {
        const float4 g = g4[j * 32 + lane];
        const bool cand = (fminf(hx2, g.z) > fmaxf(hx1, g.x)) &&
                          (fminf(hy2, g.w) > fmaxf(hy1, g.y));
        masks[j] = __ballot_sync(0xffffffffu, cand);
    }

    // ---- hit loop over candidates only ----
    float acc = -1e30f;
    #pragma unroll
    for (int j = 0; j < 4; j++) {
        unsigned m = masks[j];
        while (m) {
            const int n = j * 32 + (__ffs(m) - 1);
            m &= m - 1;
            const float4 g = g4[n];
            const float iw = fmaxf(fminf(x2p, g.z) - fmaxf(x1, g.x), 0.0f);
            const float ih = fminf(y2p, g.w) - fmaxf(y1, g.y);
            acc = fmaxf(acc, fmaf(iw, ih, -sg[n]));
        }
    }
    const bool hit = (acc >= sb);

    // ---- fix-ups (same thread as the default writes -> ordered) ----
    const int win = swin[tid];
    if (win >= 0) {
        const float4 g = g4[win];
        const float iw = fmaxf(fminf(x2p, g.z) - fmaxf(x1, g.x), 0.0f);
        const float ih = fmaxf(fminf(y2p, g.w) - fmaxf(y1, g.y), 0.0f);
        const float inter = iw * ih;
        const float ba = (x2p - x1) * (y2p - y1);
        const float iou = inter / (ba + sga[win] - inter);
        out4[t] = stbox[win];
        out[IOUS_OFF + t] = iou;
        out[BOXM_OFF + t] = 1.0f;
        out[IOUM_OFF + t] = 5.0f * (1.0f - ip);
        out[CLSM_OFF + t] = 1.0f;
    } else if (hit) {
        out[IOUM_OFF + t] = 0.0f;
    }
}

extern "C" void kernel_launch(void* const* d_in, const int* in_sizes, int n_in,
                              void* d_out, int out_size)
{
    const float4* bbox4   = (const float4*)d_in[0];
    const float*  ioup    = (const float*)d_in[1];
    const float*  gtb     = (const float*)d_in[2];
    const float*  anchors = (const float*)d_in[3];
    const int*    nboxes  = (const int*)d_in[4];
    float* out = (float*)d_out;

    static cudaStream_t s2 = [] {
        cudaStream_t s; cudaStreamCreateWithFlags(&s, cudaStreamNonBlocking);
        return s;
    }();
    static cudaEvent_t ev_fork = [] {
        cudaEvent_t e; cudaEventCreateWithFlags(&e, cudaEventDisableTiming);
        return e;
    }();
    static cudaEvent_t ev_join = [] {
        cudaEvent_t e; cudaEventCreateWithFlags(&e, cudaEventDisableTiming);
        return e;
    }();

    // fork: small-grid fill (co-resident) + full-grid compute
    cudaEventRecord(ev_fork, 0);
    cudaStreamWaitEvent(s2, ev_fork, 0);
    yolo_fill_kernel<<<FB, TPB, 0, s2>>>(gtb, anchors, nboxes, out);
    yolo_compute_kernel<<<NPRED / TPB, TPB>>>(bbox4, ioup, gtb, anchors, nboxes, out);
    cudaEventRecord(ev_join, s2);
    cudaStreamWaitEvent(0, ev_join, 0);
}